// round 1
// baseline (speedup 1.0000x reference)
#include <cuda_runtime.h>
#include <math.h>

#define NG 16
#define GS 16384   // 128*128 block stride

// ---------------- device scratch (no allocation allowed) ----------------
__device__ float g_A [NG*GS];
__device__ float g_h [NG*GS];
__device__ float g_h2[NG*GS];
__device__ float g_q [NG*GS];
__device__ float g_S [NG*GS];
__device__ float g_xs[NG*5*128];
__device__ float g_fit[NG*128];
__device__ float g_ax[NG*128];
__device__ float g_aq[NG*128];
__device__ int   g_perm[NG*128];

// ---------------- 8x8 register-tiled MM over k-major smem ----------------
// acc[ii][jj] += sum_k sA[k*128 + m0+ii] * sB[k*128 + p0+jj]
__device__ __forceinline__ void mm8x8(const float* __restrict__ sA,
                                      const float* __restrict__ sB,
                                      int K, int m0, int p0, float (&acc)[8][8]) {
  for (int k = 0; k < K; ++k) {
    const float* ar = sA + k*128 + m0;
    const float* br = sB + k*128 + p0;
    float4 a0 = *(const float4*)ar;
    float4 a1 = *(const float4*)(ar+4);
    float4 b0 = *(const float4*)br;
    float4 b1 = *(const float4*)(br+4);
    float av[8] = {a0.x,a0.y,a0.z,a0.w,a1.x,a1.y,a1.z,a1.w};
    float bv[8] = {b0.x,b0.y,b0.z,b0.w,b1.x,b1.y,b1.z,b1.w};
#pragma unroll
    for (int i=0;i<8;i++)
#pragma unroll
      for (int j=0;j<8;j++) acc[i][j] = fmaf(av[i], bv[j], acc[i][j]);
  }
}

// ---------------- utility kernels ----------------
__global__ void k_zero(float* p, int nElem){
  for (int i = blockIdx.x*blockDim.x + threadIdx.x; i < nElem; i += gridDim.x*blockDim.x)
    p[i] = 0.f;
}

__global__ void k_edges(const int* __restrict__ ei, int E, float* __restrict__ A){
  int e = blockIdx.x*blockDim.x + threadIdx.x;
  if (e < E){
    int u = ei[e], v = ei[E+e];
    int g = u >> 7;
    atomicAdd(&A[g*GS + (u&127)*128 + (v&127)], 1.0f);
  }
}

// ---------------- graph conv: h_out = relu( (A^T h / deg) Wrel^T + brel + h Wroot^T ) ----------------
__global__ void k_conv(const float* __restrict__ A, const float* __restrict__ hin,
                       int ld_in, int gstride_in, float* __restrict__ hout,
                       const float* __restrict__ wrel, const float* __restrict__ brel,
                       const float* __restrict__ wroot, int n, int Cin)
{
  extern __shared__ __align__(16) float sm[];
  float* sA = sm;            // A block (i-major), later weight (k-major)
  float* sH = sm + GS;       // h block (i-major)
  float* sG = sm + 2*GS;     // agg (k-major), later h^T (k-major)
  __shared__ float sDeg[128];
  int g = blockIdx.x, tid = threadIdx.x;
  const float* Ab = A + g*GS;
  const float* X  = hin + g*gstride_in;

  for (int idx = tid; idx < GS; idx += 256){
    int r = idx >> 7, c = idx & 127;
    sA[idx] = (r < n && c < n)   ? Ab[idx]          : 0.f;
    sH[idx] = (r < n && c < Cin) ? X[r*ld_in + c]   : 0.f;
  }
  __syncthreads();

  if (tid < 128){
    int d = 0;
    for (int i = 0; i < n; ++i) d += (sA[i*128 + tid] != 0.f);
    sDeg[tid] = fmaxf((float)d, 1.f);
  }
  __syncthreads();

  int m0 = (tid >> 4) * 8, p0 = (tid & 15) * 8;
  float acc[8][8];
#pragma unroll
  for (int i=0;i<8;i++)
#pragma unroll
    for (int j=0;j<8;j++) acc[i][j] = 0.f;

  // agg[j][c] = sum_i A[i][j] * h[i][c]
  mm8x8(sA, sH, n, m0, p0, acc);
  // store agg k-major (c-major), divided by deg[j]
#pragma unroll
  for (int ii=0; ii<8; ii++){
    int j = m0 + ii;
    if (j < n){
      float invd = 1.0f / sDeg[j];
#pragma unroll
      for (int jj=0; jj<8; jj++){
        int c = p0 + jj;
        if (c < Cin) sG[c*128 + j] = acc[ii][jj] * invd;
      }
    }
  }
  __syncthreads();

  // load wrel into sA, k-major: sA[c*128+o] = wrel[o*Cin+c]
  for (int idx = tid; idx < GS; idx += 256){
    int c = idx >> 7, o = idx & 127;
    sA[idx] = (c < Cin) ? wrel[o*Cin + c] : 0.f;
  }
  __syncthreads();

  float acc2[8][8];
#pragma unroll
  for (int i=0;i<8;i++)
#pragma unroll
    for (int j=0;j<8;j++) acc2[i][j] = 0.f;
  mm8x8(sG, sA, Cin, m0, p0, acc2);
  __syncthreads();

  // h^T into sG, wroot into sA
  for (int idx = tid; idx < GS; idx += 256){
    int c = idx >> 7, j = idx & 127;
    sG[idx] = sH[j*128 + c];
  }
  for (int idx = tid; idx < GS; idx += 256){
    int c = idx >> 7, o = idx & 127;
    sA[idx] = (c < Cin) ? wroot[o*Cin + c] : 0.f;
  }
  __syncthreads();

  mm8x8(sG, sA, Cin, m0, p0, acc2);

  float* O = hout + g*GS;
#pragma unroll
  for (int ii=0; ii<8; ii++){
    int j = m0 + ii;
    if (j < n){
#pragma unroll
      for (int jj=0; jj<8; jj++){
        int o = p0 + jj;
        O[j*128 + o] = fmaxf(acc2[ii][jj] + __ldg(brel + o), 0.f);
      }
    }
  }
}

// ---------------- group-mean pool into xs slot ----------------
__global__ void k_gpool(const float* __restrict__ h, float* __restrict__ xs, int n, int slot){
  int g = blockIdx.x, c = threadIdx.x;
  const float* H = h + g*GS;
  float s = 0.f;
  for (int i = 0; i < n; ++i) s += H[i*128 + c];
  xs[g*5*128 + slot*128 + c] = s / (float)n;
}

__global__ void k_setdiag(float* __restrict__ A, int n){
  int g = blockIdx.x, t = threadIdx.x;
  if (t < n) A[g*GS + t*128 + t] = 1.0f;
}

// ---------------- q = (masked col max) @ lin_w^T + lin_b ----------------
__global__ void k_poolq(const float* __restrict__ A, const float* __restrict__ h,
                        float* __restrict__ q, const float* __restrict__ linw,
                        const float* __restrict__ linb, int n)
{
  extern __shared__ __align__(16) float sm[];
  float* sA = sm;        // A, later lin_w k-major
  float* sH = sm + GS;   // h
  float* sQ = sm + 2*GS; // q_pre k-major
  int g = blockIdx.x, tid = threadIdx.x;
  const float* Ab = A + g*GS;
  const float* Hb = h + g*GS;

  for (int idx = tid; idx < GS; idx += 256){
    int r = idx >> 7, c = idx & 127;
    sA[idx] = (r < n && c < n) ? Ab[idx] : 0.f;
    sH[idx] = (r < n)          ? Hb[idx] : 0.f;
    (void)c;
  }
  __syncthreads();

  // q_pre[j][c] = max over i with A[i][j]!=0 of h[i][c]; store k-major sQ[c*128+j]
  for (int idx = tid; idx < GS; idx += 256){
    int j = idx & 127, c = idx >> 7;
    float best = -1e30f;
    if (j < n){
      for (int i = 0; i < n; ++i){
        if (sA[i*128 + j] != 0.f) best = fmaxf(best, sH[i*128 + c]);
      }
    } else best = 0.f;
    sQ[c*128 + j] = best;
  }
  __syncthreads();

  for (int idx = tid; idx < GS; idx += 256){
    int c = idx >> 7, o = idx & 127;
    sA[idx] = linw[o*128 + c];
  }
  __syncthreads();

  int m0 = (tid >> 4) * 8, p0 = (tid & 15) * 8;
  float acc[8][8];
#pragma unroll
  for (int i=0;i<8;i++)
#pragma unroll
    for (int j=0;j<8;j++) acc[i][j] = 0.f;
  mm8x8(sQ, sA, 128, m0, p0, acc);

  float* Q = q + g*GS;
#pragma unroll
  for (int ii=0; ii<8; ii++){
    int j = m0 + ii;
    if (j < n){
#pragma unroll
      for (int jj=0; jj<8; jj++){
        int o = p0 + jj;
        Q[j*128 + o] = acc[ii][jj] + __ldg(linb + o);
      }
    }
  }
}

// ---------------- per-node attention dots ----------------
__global__ void k_att(const float* __restrict__ h, const float* __restrict__ q,
                      const float* __restrict__ attw, float* __restrict__ ax,
                      float* __restrict__ aq, int n)
{
  int g = blockIdx.x, j = threadIdx.x;
  if (j < n){
    const float* H = h + g*GS + j*128;
    const float* Q = q + g*GS + j*128;
    float sx = 0.f, sq = 0.f;
    for (int c = 0; c < 128; ++c){
      sx = fmaf(H[c], __ldg(attw + 128 + c), sx);  // a_x = att_w[C:]
      sq = fmaf(Q[c], __ldg(attw + c), sq);        // a_q = att_w[:C]
    }
    ax[g*128 + j] = sx;
    aq[g*128 + j] = sq;
  }
}

// ---------------- masked column softmax -> S ----------------
__global__ void k_smax(const float* __restrict__ A, const float* __restrict__ ax,
                       const float* __restrict__ aq, const float* __restrict__ attb_arr,
                       int p, float* __restrict__ S, int n)
{
  int g = blockIdx.x, j = threadIdx.x;
  if (j >= n) return;
  float attb = __ldg(attb_arr + p);
  const float* Ab = A + g*GS;
  const float* axg = ax + g*128;
  float* Sb = S + g*GS;
  float ajq = aq[g*128 + j] + attb;

  float mx = -1e30f;
  for (int i = 0; i < n; ++i){
    if (Ab[i*128 + j] != 0.f){
      float l = axg[i] + ajq;
      l = (l >= 0.f) ? l : 0.2f * l;
      mx = fmaxf(mx, l);
    }
  }
  float Z = 0.f;
  for (int i = 0; i < n; ++i){
    float s = 0.f;
    if (Ab[i*128 + j] != 0.f){
      float l = axg[i] + ajq;
      l = (l >= 0.f) ? l : 0.2f * l;
      s = expf(l - mx);
      Z += s;
    }
    Sb[i*128 + j] = s;
  }
  float inv = 1.0f / Z;
  for (int i = 0; i < n; ++i) Sb[i*128 + j] *= inv;
}

// ---------------- x_new = S^T @ h ----------------
__global__ void k_xnew(const float* __restrict__ S, const float* __restrict__ h,
                       float* __restrict__ xnew, int n)
{
  extern __shared__ __align__(16) float sm[];
  float* sS = sm;
  float* sH = sm + GS;
  int g = blockIdx.x, tid = threadIdx.x;
  const float* Sb = S + g*GS;
  const float* Hb = h + g*GS;
  for (int idx = tid; idx < GS; idx += 256){
    int r = idx >> 7, c = idx & 127;
    sS[idx] = (r < n && c < n) ? Sb[idx] : 0.f;
    sH[idx] = (r < n)          ? Hb[idx] : 0.f;
  }
  __syncthreads();

  int m0 = (tid >> 4) * 8, p0 = (tid & 15) * 8;
  float acc[8][8];
#pragma unroll
  for (int i=0;i<8;i++)
#pragma unroll
    for (int j=0;j<8;j++) acc[i][j] = 0.f;
  mm8x8(sS, sH, n, m0, p0, acc);

  float* X = xnew + g*GS;
#pragma unroll
  for (int ii=0; ii<8; ii++){
    int j = m0 + ii;
    if (j < n){
#pragma unroll
      for (int jj=0; jj<8; jj++){
        int c = p0 + jj;
        X[j*128 + c] = acc[ii][jj];
      }
    }
  }
}

// ---------------- fitness = sigmoid(M^T a - deg*b + x_new@le3 + le3b) ----------------
__global__ void k_fit(const float* __restrict__ xnew, const float* __restrict__ A,
                      const float* __restrict__ le1w, const float* __restrict__ le1b_arr,
                      const float* __restrict__ le2w, const float* __restrict__ le3w,
                      const float* __restrict__ le3b_arr, int p,
                      float* __restrict__ fit, int n)
{
  __shared__ float sa[128], sb[128];
  int g = blockIdx.x, j = threadIdx.x;
  float av = 0.f, bv = 0.f, c3 = 0.f;
  if (j < n){
    const float* X = xnew + g*GS + j*128;
    for (int c = 0; c < 128; ++c){
      float x = X[c];
      av = fmaf(x, __ldg(le1w + c), av);
      bv = fmaf(x, __ldg(le2w + c), bv);
      c3 = fmaf(x, __ldg(le3w + c), c3);
    }
    av += __ldg(le1b_arr + p);
  }
  sa[j] = av; sb[j] = bv;
  __syncthreads();
  if (j < n){
    const float* Ab = A + g*GS;
    float s = 0.f, deg = 0.f;
    for (int i = 0; i < n; ++i){
      if (Ab[i*128 + j] != 0.f){ s += sa[i]; deg += 1.f; }
    }
    float f = s - deg * sb[j] + c3 + __ldg(le3b_arr + p);
    fit[g*128 + j] = 1.0f / (1.0f + expf(-f));
  }
}

// ---------------- per-group top-k (ties -> lower index), single warp ----------------
__global__ void k_topk(const float* __restrict__ fit, int* __restrict__ perm, int n, int k){
  int g = blockIdx.x, lane = threadIdx.x;
  float v[4]; bool u[4];
#pragma unroll
  for (int s = 0; s < 4; ++s){
    int j = lane + 32*s;
    v[s] = (j < n) ? fit[g*128 + j] : -3.4e38f;
    u[s] = false;
  }
  for (int r = 0; r < k; ++r){
    float bv = -3.4e38f; int bi = 1 << 30;
#pragma unroll
    for (int s = 0; s < 4; ++s){
      if (!u[s]){
        int j = lane + 32*s;
        float x = v[s];
        if (x > bv || (x == bv && j < bi)){ bv = x; bi = j; }
      }
    }
#pragma unroll
    for (int off = 16; off; off >>= 1){
      float ov = __shfl_xor_sync(0xffffffffu, bv, off);
      int   oi = __shfl_xor_sync(0xffffffffu, bi, off);
      if (ov > bv || (ov == bv && oi < bi)){ bv = ov; bi = oi; }
    }
    if ((bi & 31) == lane) u[bi >> 5] = true;
    if (lane == 0) perm[g*128 + r] = bi;
  }
}

// ---------------- gather x_out and S_sel ----------------
__global__ void k_gather(const float* __restrict__ xnew, const float* __restrict__ fit,
                         const int* __restrict__ perm, const float* __restrict__ S,
                         float* __restrict__ hout, float* __restrict__ ssel, int n, int k)
{
  int g = blockIdx.x, tid = threadIdx.x;
  for (int idx = tid; idx < k*128; idx += 256){
    int r = idx >> 7, c = idx & 127;
    int pj = perm[g*128 + r];
    hout[g*GS + r*128 + c] = xnew[g*GS + pj*128 + c] * fit[g*128 + pj];
  }
  for (int idx = tid; idx < n*128; idx += 256){
    int i = idx >> 7, r = idx & 127;
    ssel[g*GS + i*128 + r] = (r < k) ? S[g*GS + i*128 + perm[g*128 + r]] : 0.f;
  }
}

// ---------------- A2 = Ssel^T (A Ssel), diag = 1; overwrites A ----------------
__global__ void k_a2(float* __restrict__ A, const float* __restrict__ ssel, int n, int k){
  extern __shared__ __align__(16) float sm[];
  float* sAT = sm;        // A^T (k-major over m)
  float* sSs = sm + GS;   // Ssel (i-major)
  float* sT  = sm + 2*GS; // T = A @ Ssel (i-major)
  int g = blockIdx.x, tid = threadIdx.x;
  const float* Ab = A + g*GS;
  const float* Sb = ssel + g*GS;
  for (int idx = tid; idx < GS; idx += 256){
    int i = idx >> 7, m = idx & 127;
    float vv = (i < n && m < n) ? Ab[i*128 + m] : 0.f;
    sAT[m*128 + i] = vv;
    sSs[idx] = (i < n) ? Sb[idx] : 0.f;
    sT[idx] = 0.f;
  }
  __syncthreads();

  int m0 = (tid >> 4) * 8, p0 = (tid & 15) * 8;
  float acc[8][8];
#pragma unroll
  for (int i=0;i<8;i++)
#pragma unroll
    for (int j=0;j<8;j++) acc[i][j] = 0.f;
  // T[i][r] = sum_m A[i][m] Ssel[m][r]
  mm8x8(sAT, sSs, n, m0, p0, acc);
  __syncthreads();
#pragma unroll
  for (int ii=0; ii<8; ii++){
    int i = m0 + ii;
    if (i < n){
#pragma unroll
      for (int jj=0; jj<8; jj++){
        int r = p0 + jj;
        if (r < k) sT[i*128 + r] = acc[ii][jj];
      }
    }
  }
  __syncthreads();

  float acc2[8][8];
#pragma unroll
  for (int i=0;i<8;i++)
#pragma unroll
    for (int j=0;j<8;j++) acc2[i][j] = 0.f;
  // A2[r][r2] = sum_i Ssel[i][r] T[i][r2]
  mm8x8(sSs, sT, n, m0, p0, acc2);

  float* Ao = A + g*GS;
#pragma unroll
  for (int ii=0; ii<8; ii++){
    int r = m0 + ii;
    if (r < k){
#pragma unroll
      for (int jj=0; jj<8; jj++){
        int r2 = p0 + jj;
        if (r2 < k) Ao[r*128 + r2] = (r == r2) ? 1.0f : acc2[ii][jj];
      }
    }
  }
}

// ---------------- final MLP head + log_softmax ----------------
__global__ void k_head(const float* __restrict__ xs, const float* __restrict__ w1,
                       const float* __restrict__ b1, const float* __restrict__ w2,
                       const float* __restrict__ b2, float* __restrict__ out)
{
  __shared__ float z1[128];
  __shared__ float z2[2];
  int g = blockIdx.x, o = threadIdx.x;
  const float* J = xs + g*640;
  float s = __ldg(b1 + o);
  for (int c = 0; c < 640; ++c) s = fmaf(J[c], __ldg(w1 + o*640 + c), s);
  z1[o] = fmaxf(s, 0.f);
  __syncthreads();
  if (o < 2){
    float s2 = __ldg(b2 + o);
    for (int c = 0; c < 128; ++c) s2 = fmaf(z1[c], __ldg(w2 + o*128 + c), s2);
    z2[o] = s2;
  }
  __syncthreads();
  if (o == 0){
    float m = fmaxf(z2[0], z2[1]);
    float lse = m + logf(expf(z2[0] - m) + expf(z2[1] - m));
    out[g*2 + 0] = z2[0] - lse;
    out[g*2 + 1] = z2[1] - lse;
  }
}

// ---------------- host orchestration ----------------
extern "C" void kernel_launch(void* const* d_in, const int* in_sizes, int n_in,
                              void* d_out, int out_size)
{
  const float* x        = (const float*)d_in[0];
  const int*   ei       = (const int*)  d_in[1];
  const float* c0_wrel  = (const float*)d_in[2];
  const float* c0_brel  = (const float*)d_in[3];
  const float* c0_wroot = (const float*)d_in[4];
  const float* cw_rel   = (const float*)d_in[5];
  const float* cb_rel   = (const float*)d_in[6];
  const float* cw_root  = (const float*)d_in[7];
  const float* p_lin_w  = (const float*)d_in[8];
  const float* p_lin_b  = (const float*)d_in[9];
  const float* p_att_w  = (const float*)d_in[10];
  const float* p_att_b  = (const float*)d_in[11];
  const float* p_le1_w  = (const float*)d_in[12];
  const float* p_le1_b  = (const float*)d_in[13];
  const float* p_le2_w  = (const float*)d_in[14];
  const float* p_le3_w  = (const float*)d_in[15];
  const float* p_le3_b  = (const float*)d_in[16];
  const float* lin1_w   = (const float*)d_in[17];
  const float* lin1_b   = (const float*)d_in[18];
  const float* lin2_w   = (const float*)d_in[19];
  const float* lin2_b   = (const float*)d_in[20];

  float *A, *h, *h2, *q, *S, *xs, *fit, *ax, *aq;
  int* perm;
  cudaGetSymbolAddress((void**)&A,   g_A);
  cudaGetSymbolAddress((void**)&h,   g_h);
  cudaGetSymbolAddress((void**)&h2,  g_h2);
  cudaGetSymbolAddress((void**)&q,   g_q);
  cudaGetSymbolAddress((void**)&S,   g_S);
  cudaGetSymbolAddress((void**)&xs,  g_xs);
  cudaGetSymbolAddress((void**)&fit, g_fit);
  cudaGetSymbolAddress((void**)&ax,  g_ax);
  cudaGetSymbolAddress((void**)&aq,  g_aq);
  cudaGetSymbolAddress((void**)&perm, g_perm);

  const size_t SM3 = 3 * GS * sizeof(float);
  const size_t SM2 = 2 * GS * sizeof(float);
  cudaFuncSetAttribute(k_conv,  cudaFuncAttributeMaxDynamicSharedMemorySize, (int)SM3);
  cudaFuncSetAttribute(k_poolq, cudaFuncAttributeMaxDynamicSharedMemorySize, (int)SM3);
  cudaFuncSetAttribute(k_xnew,  cudaFuncAttributeMaxDynamicSharedMemorySize, (int)SM2);
  cudaFuncSetAttribute(k_a2,    cudaFuncAttributeMaxDynamicSharedMemorySize, (int)SM3);

  int E = in_sizes[1] / 2;

  k_zero<<<256, 256>>>(A, NG*GS);
  k_edges<<<(E + 255)/256, 256>>>(ei, E, A);

  // conv0: IN_CH=64 -> HID=128
  k_conv<<<NG, 256, SM3>>>(A, x, 64, 128*64, h, c0_wrel, c0_brel, c0_wroot, 128, 64);
  k_gpool<<<NG, 128>>>(h, xs, 128, 0);

  int n = 128;
  int p = 0;
  const int ks[2] = {103, 83};

  for (int i = 0; i < 4; ++i){
    k_conv<<<NG, 256, SM3>>>(A, h, 128, GS, h,
                             cw_rel + i*128*128, cb_rel + i*128, cw_root + i*128*128,
                             n, 128);
    k_gpool<<<NG, 128>>>(h, xs, n, i + 1);
    if (i % 2 == 0 && i < 3){
      int k = ks[p];
      k_setdiag<<<NG, 128>>>(A, n);
      k_poolq<<<NG, 256, SM3>>>(A, h, q, p_lin_w + p*128*128, p_lin_b + p*128, n);
      k_att<<<NG, 128>>>(h, q, p_att_w + p*256, ax, aq, n);
      k_smax<<<NG, 128>>>(A, ax, aq, p_att_b, p, S, n);
      k_xnew<<<NG, 256, SM2>>>(S, h, h2, n);
      k_fit<<<NG, 128>>>(h2, A, p_le1_w + p*128, p_le1_b, p_le2_w + p*128,
                         p_le3_w + p*128, p_le3_b, p, fit, n);
      k_topk<<<NG, 32>>>(fit, perm, n, k);
      k_gather<<<NG, 256>>>(h2, fit, perm, S, h, q, n, k);
      k_a2<<<NG, 256, SM3>>>(A, q, n, k);
      n = k;
      ++p;
    }
  }

  k_head<<<NG, 128>>>(xs, lin1_w, lin1_b, lin2_w, lin2_b, (float*)d_out);
}

// round 2
// speedup vs baseline: 2.1650x; 2.1650x over previous
#include <cuda_runtime.h>
#include <math.h>

#define NG 16
#define GS 16384   // 128*128 block stride

// ---------------- device scratch ----------------
__device__ float g_A  [NG*GS];
__device__ float g_h  [NG*GS];
__device__ float g_hb [NG*GS];
__device__ float g_x2 [NG*GS];   // xnew
__device__ float g_S  [NG*GS];
__device__ float g_T  [NG*GS];
__device__ float g_wt [12*GS];   // transposed weights
__device__ float g_w1t[640*128];
__device__ float g_xs [NG*5*128];
__device__ float g_fit[NG*128];
__device__ float g_ax [NG*128];
__device__ float g_aq [NG*128];
__device__ int   g_perm[NG*128];

__device__ __forceinline__ void fma8(float a, const float* b, float acc[8]){
  float4 b0 = *(const float4*)b;
  float4 b1 = *(const float4*)(b+4);
  acc[0]=fmaf(a,b0.x,acc[0]); acc[1]=fmaf(a,b0.y,acc[1]);
  acc[2]=fmaf(a,b0.z,acc[2]); acc[3]=fmaf(a,b0.w,acc[3]);
  acc[4]=fmaf(a,b1.x,acc[4]); acc[5]=fmaf(a,b1.y,acc[5]);
  acc[6]=fmaf(a,b1.z,acc[6]); acc[7]=fmaf(a,b1.w,acc[7]);
}

// ---------------- weight transposes ----------------
__global__ void k_wprep(const float* __restrict__ c0r, const float* __restrict__ c0t,
                        const float* __restrict__ cwr, const float* __restrict__ cwt,
                        const float* __restrict__ plw){
  int slot = blockIdx.x;
  int idx = blockIdx.y*256 + threadIdx.x;     // < 16384
  int c = idx >> 7, o = idx & 127;
  const float* src; int Cin;
  if (slot == 0){ src = c0r; Cin = 64; }
  else if (slot == 1){ src = c0t; Cin = 64; }
  else if (slot < 6){ src = cwr + (slot-2)*GS; Cin = 128; }
  else if (slot < 10){ src = cwt + (slot-6)*GS; Cin = 128; }
  else { src = plw + (slot-10)*GS; Cin = 128; }
  g_wt[slot*GS + idx] = (c < Cin) ? src[o*Cin + c] : 0.f;
}

__global__ void k_w1prep(const float* __restrict__ w1){
  int idx = blockIdx.x*256 + threadIdx.x;     // < 81920
  int c = idx >> 7, o = idx & 127;
  g_w1t[idx] = w1[o*640 + c];
}

__global__ void k_zero(){
  int idx = blockIdx.x*blockDim.x + threadIdx.x;
  if (idx < NG*GS) g_A[idx] = 0.f;
  if (idx < NG*5*128) g_xs[idx] = 0.f;
}

__global__ void k_edges(const int* __restrict__ ei, int E){
  int e = blockIdx.x*blockDim.x + threadIdx.x;
  if (e < E){
    int u = ei[e], v = ei[E+e];
    int g = u >> 7;
    atomicAdd(&g_A[g*GS + (u&127)*128 + (v&127)], 1.0f);
  }
}

__global__ void k_setdiag(int n){
  int g = blockIdx.x, t = threadIdx.x;
  if (t < n) g_A[g*GS + t*128 + t] = 1.0f;
}

// ---------------- graph conv (tiled: 16 rows/CTA) + fused gpool ----------------
__global__ void k_conv(const float* __restrict__ hin, int ld_in, int gstride_in,
                       float* __restrict__ hout,
                       const float* __restrict__ wtrel, const float* __restrict__ wtroot,
                       const float* __restrict__ brel, int slot, int n, int Cin, float invn)
{
  extern __shared__ float sm[];
  float* sH   = sm;                 // 16384
  float* sW   = sm + 16384;         // 16384
  float* sAc  = sW + 16384;         // 2048  (128 x 16)
  float* sAgg = sAc + 2048;         // 2176  (128 x 17)
  float* sHt  = sAgg + 2176;        // 2176
  float* sDeg = sHt + 2176;         // 16
  int g = blockIdx.x, t = blockIdx.y, tid = threadIdx.x;
  int j0 = t*16;
  if (j0 >= n) return;
  const float* X = hin + g*gstride_in;

  if (Cin == 128){
    const float4* src4 = (const float4*)X;
    float4* dst4 = (float4*)sH;
    for (int i4 = tid; i4 < n*32; i4 += 256) dst4[i4] = src4[i4];
  } else {
    for (int idx = tid; idx < n*128; idx += 256){
      int i = idx >> 7, c = idx & 127;
      sH[idx] = (c < Cin) ? X[i*ld_in + c] : 0.f;
    }
  }
  for (int idx = tid; idx < n*16; idx += 256){
    int i = idx >> 4, jt = idx & 15;
    int j = j0 + jt;
    sAc[idx] = (j < n) ? g_A[g*GS + i*128 + j] : 0.f;
  }
  __syncthreads();
  if (tid < 16){
    int d = 0;
    for (int i = 0; i < n; ++i) d += (sAc[i*16 + tid] != 0.f);
    sDeg[tid] = fmaxf((float)d, 1.f);
  }
  __syncthreads();

  int jt = tid >> 4, c0 = (tid & 15) * 8;
  float acc[8] = {0,0,0,0,0,0,0,0};
  for (int k = 0; k < n; ++k){
    float a = sAc[k*16 + jt];
    if (a != 0.f) fma8(a, &sH[k*128 + c0], acc);
  }
  {
    float invd = 1.f / sDeg[jt];
    int j = j0 + jt;
#pragma unroll
    for (int u = 0; u < 8; ++u){
      sAgg[(c0+u)*17 + jt] = acc[u] * invd;
      sHt [(c0+u)*17 + jt] = (j < n) ? sH[j*128 + c0 + u] : 0.f;
    }
  }
  __syncthreads();
  {
    const float4* w4 = (const float4*)wtrel;
    float4* s4 = (float4*)sW;
    for (int i4 = tid; i4 < Cin*32; i4 += 256) s4[i4] = w4[i4];
  }
  __syncthreads();
  float acc2[8] = {0,0,0,0,0,0,0,0};
  for (int k = 0; k < Cin; ++k)
    fma8(sAgg[k*17 + jt], &sW[k*128 + c0], acc2);
  __syncthreads();
  {
    const float4* w4 = (const float4*)wtroot;
    float4* s4 = (float4*)sW;
    for (int i4 = tid; i4 < Cin*32; i4 += 256) s4[i4] = w4[i4];
  }
  __syncthreads();
  for (int k = 0; k < Cin; ++k)
    fma8(sHt[k*17 + jt], &sW[k*128 + c0], acc2);

  // epilogue: relu + store + fused gpool partial sum
  int j = j0 + jt;
  if (j < n){
#pragma unroll
    for (int u = 0; u < 8; ++u){
      float v = fmaxf(acc2[u] + __ldg(brel + c0 + u), 0.f);
      hout[g*GS + j*128 + c0 + u] = v;
      sAgg[(c0+u)*17 + jt] = v;
    }
  } else {
#pragma unroll
    for (int u = 0; u < 8; ++u) sAgg[(c0+u)*17 + jt] = 0.f;
  }
  __syncthreads();
  if (tid < 128){
    float s = 0.f;
#pragma unroll
    for (int q = 0; q < 16; ++q) s += sAgg[tid*17 + q];
    atomicAdd(&g_xs[g*640 + slot*128 + tid], s * invn);
  }
}

// ---------------- poolq (masked col-max @ lin) + attention dots ----------------
__global__ void k_poolq(const float* __restrict__ h, const float* __restrict__ wt,
                        const float* __restrict__ linb, const float* __restrict__ attw, int n)
{
  extern __shared__ float sm[];
  float* sH  = sm;            // 16384
  float* sW  = sm + 16384;    // 16384
  float* sAc = sW + 16384;    // 2048
  float* sQt = sAc + 2048;    // 2176
  float* sQr = sQt + 2176;    // 16*136 = 2176
  int g = blockIdx.x, t = blockIdx.y, tid = threadIdx.x;
  int j0 = t*16; if (j0 >= n) return;

  {
    const float4* h4 = (const float4*)(h + g*GS);
    float4* s4 = (float4*)sH;
    for (int i4 = tid; i4 < n*32; i4 += 256) s4[i4] = h4[i4];
  }
  for (int idx = tid; idx < n*16; idx += 256){
    int i = idx >> 4, jt2 = idx & 15;
    int j = j0 + jt2;
    sAc[idx] = (j < n) ? g_A[g*GS + i*128 + j] : 0.f;
  }
  {
    const float4* w4 = (const float4*)wt;
    float4* s4 = (float4*)sW;
    for (int i4 = tid; i4 < 4096; i4 += 256) s4[i4] = w4[i4];
  }
  __syncthreads();

  int jt = tid >> 4, c0 = (tid & 15) * 8;
  float mx[8];
#pragma unroll
  for (int u = 0; u < 8; ++u) mx[u] = -1e30f;
  for (int i = 0; i < n; ++i){
    if (sAc[i*16 + jt] != 0.f){
      float4 b0 = *(const float4*)&sH[i*128 + c0];
      float4 b1 = *(const float4*)&sH[i*128 + c0 + 4];
      mx[0]=fmaxf(mx[0],b0.x); mx[1]=fmaxf(mx[1],b0.y);
      mx[2]=fmaxf(mx[2],b0.z); mx[3]=fmaxf(mx[3],b0.w);
      mx[4]=fmaxf(mx[4],b1.x); mx[5]=fmaxf(mx[5],b1.y);
      mx[6]=fmaxf(mx[6],b1.z); mx[7]=fmaxf(mx[7],b1.w);
    }
  }
#pragma unroll
  for (int u = 0; u < 8; ++u) sQt[(c0+u)*17 + jt] = mx[u];
  __syncthreads();

  float acc[8] = {0,0,0,0,0,0,0,0};
  for (int k = 0; k < 128; ++k)
    fma8(sQt[k*17 + jt], &sW[k*128 + c0], acc);
#pragma unroll
  for (int u = 0; u < 8; ++u) sQr[jt*136 + c0 + u] = acc[u] + __ldg(linb + c0 + u);
  __syncthreads();

  if (tid < 16){
    int j = j0 + tid;
    if (j < n){
      float sq = 0.f, sx = 0.f;
      for (int c = 0; c < 128; ++c){
        sq = fmaf(sQr[tid*136 + c], __ldg(attw + c), sq);        // a_q = att_w[:C]
        sx = fmaf(sH[j*128 + c],    __ldg(attw + 128 + c), sx);  // a_x = att_w[C:]
      }
      g_aq[g*128 + j] = sq;
      g_ax[g*128 + j] = sx;
    }
  }
}

// ---------------- masked column softmax + x_new = S^T h ----------------
__global__ void k_smaxx(const float* __restrict__ h, const float* __restrict__ attb, int p, int n)
{
  extern __shared__ float sm[];
  float* sH   = sm;           // 16384
  float* sAc  = sm + 16384;   // 2048
  float* sS   = sAc + 2048;   // 2176
  float* sax  = sS + 2176;    // 128
  float* sInv = sax + 128;    // 16
  int g = blockIdx.x, t = blockIdx.y, tid = threadIdx.x;
  int j0 = t*16; if (j0 >= n) return;

  {
    const float4* h4 = (const float4*)(h + g*GS);
    float4* s4 = (float4*)sH;
    for (int i4 = tid; i4 < n*32; i4 += 256) s4[i4] = h4[i4];
  }
  for (int idx = tid; idx < n*16; idx += 256){
    int i = idx >> 4, jt2 = idx & 15;
    int j = j0 + jt2;
    sAc[idx] = (j < n) ? g_A[g*GS + i*128 + j] : 0.f;
  }
  if (tid < n) sax[tid] = g_ax[g*128 + tid];
  __syncthreads();

  if (tid < 16){
    int j = j0 + tid;
    if (j < n){
      float ajq = g_aq[g*128 + j] + __ldg(attb + p);
      float mxv = -1e30f;
      for (int i = 0; i < n; ++i){
        if (sAc[i*16 + tid] != 0.f){
          float l = sax[i] + ajq;
          l = (l >= 0.f) ? l : 0.2f*l;
          mxv = fmaxf(mxv, l);
        }
      }
      float Z = 0.f;
      for (int i = 0; i < n; ++i){
        float s = 0.f;
        if (sAc[i*16 + tid] != 0.f){
          float l = sax[i] + ajq;
          l = (l >= 0.f) ? l : 0.2f*l;
          s = expf(l - mxv);
          Z += s;
        }
        sS[i*17 + tid] = s;
      }
      sInv[tid] = 1.f / Z;
    } else sInv[tid] = 0.f;
  }
  __syncthreads();

  // normalized S tile -> global
  for (int idx = tid; idx < n*16; idx += 256){
    int i = idx >> 4, jj = idx & 15;
    int j = j0 + jj;
    if (j < n) g_S[g*GS + i*128 + j] = sS[i*17 + jj] * sInv[jj];
  }
  // x_new rows
  int jt = tid >> 4, c0 = (tid & 15) * 8;
  float acc[8] = {0,0,0,0,0,0,0,0};
  for (int k = 0; k < n; ++k){
    float a = sS[k*17 + jt];
    if (a != 0.f) fma8(a, &sH[k*128 + c0], acc);
  }
  int j = j0 + jt;
  if (j < n){
    float inv = sInv[jt];
#pragma unroll
    for (int u = 0; u < 8; ++u) g_x2[g*GS + j*128 + c0 + u] = acc[u] * inv;
  }
}

// ---------------- fitness + top-k ----------------
__global__ void k_fitk(const float* __restrict__ le1w, const float* __restrict__ le1b,
                       const float* __restrict__ le2w, const float* __restrict__ le3w,
                       const float* __restrict__ le3b, int p, int n, int k)
{
  __shared__ float sa[128], sb[128], sfit[128];
  int g = blockIdx.x, j = threadIdx.x;   // 128 threads
  float av = 0.f, bv = 0.f, c3 = 0.f;
  if (j < n){
    const float* X = g_x2 + g*GS + j*128;
    for (int c = 0; c < 128; ++c){
      float x = X[c];
      av = fmaf(x, __ldg(le1w + c), av);
      bv = fmaf(x, __ldg(le2w + c), bv);
      c3 = fmaf(x, __ldg(le3w + c), c3);
    }
    av += __ldg(le1b + p);
  }
  sa[j] = av; sb[j] = bv;
  __syncthreads();
  if (j < n){
    const float* Ab = g_A + g*GS;
    float s = 0.f, deg = 0.f;
    for (int i = 0; i < n; ++i){
      if (Ab[i*128 + j] != 0.f){ s += sa[i]; deg += 1.f; }
    }
    float f = s - deg*sb[j] + c3 + __ldg(le3b + p);
    float ff = 1.f / (1.f + expf(-f));
    sfit[j] = ff;
    g_fit[g*128 + j] = ff;
  } else sfit[j] = -3.4e38f;
  __syncthreads();
  if (j < 32){
    int lane = j;
    float v[4]; bool used[4];
#pragma unroll
    for (int s2 = 0; s2 < 4; ++s2){ v[s2] = sfit[lane + 32*s2]; used[s2] = false; }
    for (int r = 0; r < k; ++r){
      float bvv = -3.4e38f; int bi = 1 << 30;
#pragma unroll
      for (int s2 = 0; s2 < 4; ++s2){
        if (!used[s2]){
          int jj = lane + 32*s2;
          float xv = v[s2];
          if (xv > bvv || (xv == bvv && jj < bi)){ bvv = xv; bi = jj; }
        }
      }
#pragma unroll
      for (int off = 16; off; off >>= 1){
        float ov = __shfl_xor_sync(0xffffffffu, bvv, off);
        int   oi = __shfl_xor_sync(0xffffffffu, bi, off);
        if (ov > bvv || (ov == bvv && oi < bi)){ bvv = ov; bi = oi; }
      }
      if ((bi & 31) == lane) used[bi >> 5] = true;
      if (lane == 0) g_perm[g*128 + r] = bi;
    }
  }
}

// ---------------- T = A @ Ssel (tiled) + gather hout ----------------
__global__ void k_aS(float* __restrict__ hout, int n, int k)
{
  extern __shared__ float sm[];
  float* sSel = sm;           // 16384
  float* sAt  = sm + 16384;   // 2176
  __shared__ int sperm[128];
  int g = blockIdx.x, t = blockIdx.y, tid = threadIdx.x;
  int i0 = t*16; if (i0 >= n) return;
  if (tid < k) sperm[tid] = g_perm[g*128 + tid];
  __syncthreads();
  for (int idx = tid; idx < n*128; idx += 256){
    int m = idx >> 7, r = idx & 127;
    sSel[idx] = (r < k) ? g_S[g*GS + m*128 + sperm[r]] : 0.f;
  }
  for (int idx = tid; idx < 16*128; idx += 256){
    int it = idx >> 7, m = idx & 127;
    sAt[m*17 + it] = g_A[g*GS + (i0+it)*128 + m];
  }
  __syncthreads();
  int it = tid >> 4, r0 = (tid & 15) * 8;
  float acc[8] = {0,0,0,0,0,0,0,0};
  for (int m = 0; m < n; ++m){
    float a = sAt[m*17 + it];
    if (a != 0.f) fma8(a, &sSel[m*128 + r0], acc);
  }
  int i = i0 + it;
  if (i < n){
#pragma unroll
    for (int u = 0; u < 8; ++u) g_T[g*GS + i*128 + r0 + u] = acc[u];
  }
  // gather x_out rows for this tile
  for (int idx = tid; idx < 16*128; idx += 256){
    int rt = idx >> 7, c = idx & 127;
    int r = i0 + rt;
    if (r < k){
      int pj = sperm[r];
      hout[g*GS + r*128 + c] = g_x2[g*GS + pj*128 + c] * g_fit[g*128 + pj];
    }
  }
}

// ---------------- A2 = Ssel^T @ T, diag=1 (tiled) ----------------
__global__ void k_sTs(int n, int k)
{
  extern __shared__ float sm[];
  float* sT  = sm;            // 16384
  float* sSa = sm + 16384;    // 2176
  __shared__ int sperm[128];
  int g = blockIdx.x, t = blockIdx.y, tid = threadIdx.x;
  int r0 = t*16; if (r0 >= k) return;
  if (tid < k) sperm[tid] = g_perm[g*128 + tid];
  __syncthreads();
  {
    const float4* t4 = (const float4*)(g_T + g*GS);
    float4* s4 = (float4*)sT;
    for (int i4 = tid; i4 < n*32; i4 += 256) s4[i4] = t4[i4];
  }
  for (int idx = tid; idx < n*16; idx += 256){
    int i = idx >> 4, rt2 = idx & 15;
    int r = r0 + rt2;
    sSa[i*17 + rt2] = (r < k) ? g_S[g*GS + i*128 + sperm[r]] : 0.f;
  }
  __syncthreads();
  int rt = tid >> 4, c0 = (tid & 15) * 8;
  float acc[8] = {0,0,0,0,0,0,0,0};
  for (int i = 0; i < n; ++i){
    float a = sSa[i*17 + rt];
    if (a != 0.f) fma8(a, &sT[i*128 + c0], acc);
  }
  int r = r0 + rt;
  if (r < k){
#pragma unroll
    for (int u = 0; u < 8; ++u){
      int r2 = c0 + u;
      float v = (r2 == r) ? 1.f : acc[u];
      g_A[g*GS + r*128 + r2] = (r2 < k) ? v : 0.f;
    }
  }
}

// ---------------- final MLP head + log_softmax ----------------
__global__ void k_head(const float* __restrict__ b1, const float* __restrict__ w2,
                       const float* __restrict__ b2, float* __restrict__ out)
{
  __shared__ float sJ[640];
  __shared__ float z1[128];
  __shared__ float z2[2];
  int g = blockIdx.x, o = threadIdx.x;   // 128 threads
  for (int c = o; c < 640; c += 128) sJ[c] = g_xs[g*640 + c];
  __syncthreads();
  float s = __ldg(b1 + o);
  for (int c = 0; c < 640; ++c) s = fmaf(sJ[c], g_w1t[c*128 + o], s);
  z1[o] = fmaxf(s, 0.f);
  __syncthreads();
  if (o < 2){
    float s2 = __ldg(b2 + o);
    for (int c = 0; c < 128; ++c) s2 = fmaf(z1[c], __ldg(w2 + o*128 + c), s2);
    z2[o] = s2;
  }
  __syncthreads();
  if (o == 0){
    float m = fmaxf(z2[0], z2[1]);
    float lse = m + logf(expf(z2[0] - m) + expf(z2[1] - m));
    out[g*2 + 0] = z2[0] - lse;
    out[g*2 + 1] = z2[1] - lse;
  }
}

// ---------------- host orchestration ----------------
extern "C" void kernel_launch(void* const* d_in, const int* in_sizes, int n_in,
                              void* d_out, int out_size)
{
  const float* x        = (const float*)d_in[0];
  const int*   ei       = (const int*)  d_in[1];
  const float* c0_wrel  = (const float*)d_in[2];
  const float* c0_brel  = (const float*)d_in[3];
  const float* c0_wroot = (const float*)d_in[4];
  const float* cw_rel   = (const float*)d_in[5];
  const float* cb_rel   = (const float*)d_in[6];
  const float* cw_root  = (const float*)d_in[7];
  const float* p_lin_w  = (const float*)d_in[8];
  const float* p_lin_b  = (const float*)d_in[9];
  const float* p_att_w  = (const float*)d_in[10];
  const float* p_att_b  = (const float*)d_in[11];
  const float* p_le1_w  = (const float*)d_in[12];
  const float* p_le1_b  = (const float*)d_in[13];
  const float* p_le2_w  = (const float*)d_in[14];
  const float* p_le3_w  = (const float*)d_in[15];
  const float* p_le3_b  = (const float*)d_in[16];
  const float* lin1_w   = (const float*)d_in[17];
  const float* lin1_b   = (const float*)d_in[18];
  const float* lin2_w   = (const float*)d_in[19];
  const float* lin2_b   = (const float*)d_in[20];

  float *wt, *hA, *hB;
  cudaGetSymbolAddress((void**)&wt, g_wt);
  cudaGetSymbolAddress((void**)&hA, g_h);
  cudaGetSymbolAddress((void**)&hB, g_hb);

  const size_t SM_CONV  = (size_t)(16384+16384+2048+2176+2176+16)*4;
  const size_t SM_POOLQ = (size_t)(16384+16384+2048+2176+2176)*4;
  const size_t SM_SMAXX = (size_t)(16384+2048+2176+128+16)*4;
  const size_t SM_AS    = (size_t)(16384+2176)*4;
  cudaFuncSetAttribute(k_conv,  cudaFuncAttributeMaxDynamicSharedMemorySize, (int)SM_CONV);
  cudaFuncSetAttribute(k_poolq, cudaFuncAttributeMaxDynamicSharedMemorySize, (int)SM_POOLQ);
  cudaFuncSetAttribute(k_smaxx, cudaFuncAttributeMaxDynamicSharedMemorySize, (int)SM_SMAXX);
  cudaFuncSetAttribute(k_aS,    cudaFuncAttributeMaxDynamicSharedMemorySize, (int)SM_AS);
  cudaFuncSetAttribute(k_sTs,   cudaFuncAttributeMaxDynamicSharedMemorySize, (int)SM_AS);

  int E = in_sizes[1] / 2;
  dim3 gT(NG, 8);

  k_wprep<<<dim3(12,64), 256>>>(c0_wrel, c0_wroot, cw_rel, cw_root, p_lin_w);
  k_w1prep<<<320, 256>>>(lin1_w);
  k_zero<<<1024, 256>>>();
  k_edges<<<(E + 255)/256, 256>>>(ei, E);

  // conv0: 64 -> 128, x -> hA
  k_conv<<<gT, 256, SM_CONV>>>(x, 64, 128*64, hA, wt + 0*GS, wt + 1*GS, c0_brel, 0, 128, 64, 1.f/128.f);
  // conv i=0: hA -> hB
  k_conv<<<gT, 256, SM_CONV>>>(hA, 128, GS, hB, wt + 2*GS, wt + 6*GS, cb_rel + 0, 1, 128, 128, 1.f/128.f);

  // ---- pool 1 (n=128 -> k=103), h = hB, x_out -> hA ----
  k_setdiag<<<NG, 128>>>(128);
  k_poolq<<<gT, 256, SM_POOLQ>>>(hB, wt + 10*GS, p_lin_b + 0, p_att_w + 0, 128);
  k_smaxx<<<gT, 256, SM_SMAXX>>>(hB, p_att_b, 0, 128);
  k_fitk<<<NG, 128>>>(p_le1_w + 0, p_le1_b, p_le2_w + 0, p_le3_w + 0, p_le3_b, 0, 128, 103);
  k_aS<<<gT, 256, SM_AS>>>(hA, 128, 103);
  k_sTs<<<gT, 256, SM_AS>>>(128, 103);

  // conv i=1: hA -> hB (n=103)
  k_conv<<<gT, 256, SM_CONV>>>(hA, 128, GS, hB, wt + 3*GS, wt + 7*GS, cb_rel + 128, 2, 103, 128, 1.f/103.f);
  // conv i=2: hB -> hA
  k_conv<<<gT, 256, SM_CONV>>>(hB, 128, GS, hA, wt + 4*GS, wt + 8*GS, cb_rel + 256, 3, 103, 128, 1.f/103.f);

  // ---- pool 2 (n=103 -> k=83), h = hA, x_out -> hB ----
  k_poolq<<<gT, 256, SM_POOLQ>>>(hA, wt + 11*GS, p_lin_b + 128, p_att_w + 256, 103);
  k_smaxx<<<gT, 256, SM_SMAXX>>>(hA, p_att_b, 1, 103);
  k_fitk<<<NG, 128>>>(p_le1_w + 128, p_le1_b, p_le2_w + 128, p_le3_w + 128, p_le3_b, 1, 103, 83);
  k_aS<<<gT, 256, SM_AS>>>(hB, 103, 83);
  k_sTs<<<gT, 256, SM_AS>>>(103, 83);

  // conv i=3: hB -> hA (n=83)
  k_conv<<<gT, 256, SM_CONV>>>(hB, 128, GS, hA, wt + 5*GS, wt + 9*GS, cb_rel + 384, 4, 83, 128, 1.f/83.f);

  k_head<<<NG, 128>>>(lin1_b, lin2_w, lin2_b, (float*)d_out);
}